// round 13
// baseline (speedup 1.0000x reference)
#include <cuda_runtime.h>
#include <cuda_bf16.h>
#include <cstdint>

// Problem constants (fixed by the dataset)
#define BB    2
#define NQ    21760
#define NKTOT 21760
#define DIM   256
#define NH    8
#define NL    4
#define NPNT  4
#define BQ    (BB * NQ)            // 43520

// Hardcoded level geometry (SHAPES = [(128,128),(64,64),(32,32),(16,16)])
__device__ __constant__ int c_HW[NL]  = {128, 64, 32, 16};
__device__ __constant__ int c_LSI[NL] = {0, 16384, 20480, 21504};

// Output layout: [output | loc | attn]
#define OUT_OFF  0
#define LOC_OFF  (BQ * DIM)
#define ATTN_OFF (BQ * DIM * 2)

// Scratch (allocation-free: device globals)
__device__ float g_value[BQ * DIM];
__device__ float g_off[BQ * DIM];
__device__ float g_core[BQ * DIM];
// Pre-transposed, bf16-split weights: [w][N][K] with K=256, N<=256
__device__ __nv_bfloat16 g_wthi[4 * 256 * 256];
__device__ __nv_bfloat16 g_wtlo[4 * 256 * 256];

// fp32 -> (hi, lo) bf16 pair, packed 2-at-a-time
__device__ __forceinline__ void cvt2_split(float a, float b, uint32_t& hi, uint32_t& lo) {
    __nv_bfloat162 h = __floats2bfloat162_rn(a, b);
    float ra = a - __bfloat162float(h.x);
    float rb = b - __bfloat162float(h.y);
    __nv_bfloat162 l = __floats2bfloat162_rn(ra, rb);
    hi = *reinterpret_cast<uint32_t*>(&h);
    lo = *reinterpret_cast<uint32_t*>(&l);
}

// m16n8k16 bf16 MMA, fp32 accumulate (HMMA; valid on base sm_103 target)
__device__ __forceinline__ void mma16816(float* c, const uint32_t* a, const uint32_t* b) {
    asm volatile(
        "mma.sync.aligned.m16n8k16.row.col.f32.bf16.bf16.f32 "
        "{%0,%1,%2,%3}, {%4,%5,%6,%7}, {%8,%9}, {%0,%1,%2,%3};\n"
        : "+f"(c[0]), "+f"(c[1]), "+f"(c[2]), "+f"(c[3])
        : "r"(a[0]), "r"(a[1]), "r"(a[2]), "r"(a[3]), "r"(b[0]), "r"(b[1]));
}

// ---------------------------------------------------------------------------
// Weight prep: Wt[n][k] = split(W[k][n]) for the 4 weight matrices.
// ---------------------------------------------------------------------------
__global__ void prep_weights(const float* __restrict__ Wv, const float* __restrict__ Woff,
                             const float* __restrict__ Wattn, const float* __restrict__ Wout)
{
    const int w = blockIdx.y;
    const int n = blockIdx.x;
    const int Nw = (w == 2) ? 128 : 256;
    if (n >= Nw) return;
    const float* W = (w == 0) ? Wv : (w == 1) ? Woff : (w == 2) ? Wattn : Wout;
    const int k = threadIdx.x;
    const float v = W[k * Nw + n];
    const __nv_bfloat16 h = __float2bfloat16(v);
    g_wthi[w * 65536 + n * 256 + k] = h;
    g_wtlo[w * 65536 + n * 256 + k] = __float2bfloat16(v - __bfloat162float(h));
}

// ---------------------------------------------------------------------------
// bf16x3 HMMA GEMM: C[M, NC] = A[M, 256] @ Wt^T + bias  (Wt is [NC, 256] bf16)
// CTA: 256 thr = 8 warps (4 M x 2 N), tile 128x128, warp tile 32x64.
// K staged in 32-chunks; A split fp32->bf16 hi/lo during staging.
// Smem rows padded to 40 elems -> conflict-free m16n8k16 fragment loads.
// ---------------------------------------------------------------------------
template<int NC>
__global__ __launch_bounds__(256) void gemm_mma(
    const float* __restrict__ A,
    const __nv_bfloat16* __restrict__ Bhi_g, const __nv_bfloat16* __restrict__ Blo_g,
    const float* __restrict__ bias, float* __restrict__ C)
{
    constexpr int LP = 40;  // padded smem row stride (bf16 elements)
    __shared__ __align__(16) __nv_bfloat16 sAhi[128 * LP];
    __shared__ __align__(16) __nv_bfloat16 sAlo[128 * LP];
    __shared__ __align__(16) __nv_bfloat16 sBhi[128 * LP];
    __shared__ __align__(16) __nv_bfloat16 sBlo[128 * LP];

    const int t     = threadIdx.x;
    const int lane  = t & 31;
    const int warp  = t >> 5;
    const int warpM = warp & 3;          // 0..3
    const int warpN = warp >> 2;         // 0..1
    const int g     = lane >> 2;         // 0..7
    const int tc    = (lane & 3) << 1;   // 0,2,4,6
    const int m0    = blockIdx.y * 128;
    const int n0    = blockIdx.x * 128;
    const int mbase = warpM * 32;
    const int nbase = warpN * 64;

    float acc[2][8][4];
    #pragma unroll
    for (int i = 0; i < 2; ++i)
        #pragma unroll
        for (int j = 0; j < 8; ++j)
            #pragma unroll
            for (int k = 0; k < 4; ++k) acc[i][j][k] = 0.f;

    for (int kc = 0; kc < 256; kc += 32) {
        // Stage A: 128x32 fp32 -> hi/lo bf16 (4 float4 per thread)
        #pragma unroll
        for (int i = 0; i < 4; ++i) {
            const int idx = t + i * 256;
            const int row = idx >> 3;
            const int col = (idx & 7) << 2;
            const float4 f = *(const float4*)&A[(size_t)(m0 + row) * 256 + kc + col];
            uint32_t h0, l0, h1, l1;
            cvt2_split(f.x, f.y, h0, l0);
            cvt2_split(f.z, f.w, h1, l1);
            const int off = row * LP + col;
            *(uint32_t*)&sAhi[off]     = h0;
            *(uint32_t*)&sAhi[off + 2] = h1;
            *(uint32_t*)&sAlo[off]     = l0;
            *(uint32_t*)&sAlo[off + 2] = l1;
        }
        // Stage B: 128x32 bf16 hi/lo (2 uint4 per thread per tensor)
        #pragma unroll
        for (int i = 0; i < 2; ++i) {
            const int idx = t + i * 256;
            const int row = idx >> 2;
            const int col = (idx & 3) << 3;
            const uint4 h = *(const uint4*)&Bhi_g[(size_t)(n0 + row) * 256 + kc + col];
            const uint4 l = *(const uint4*)&Blo_g[(size_t)(n0 + row) * 256 + kc + col];
            const int off = row * LP + col;
            *(uint2*)&sBhi[off]     = make_uint2(h.x, h.y);
            *(uint2*)&sBhi[off + 4] = make_uint2(h.z, h.w);
            *(uint2*)&sBlo[off]     = make_uint2(l.x, l.y);
            *(uint2*)&sBlo[off + 4] = make_uint2(l.z, l.w);
        }
        __syncthreads();

        #pragma unroll
        for (int ks = 0; ks < 2; ++ks) {
            const int kb = ks * 16;
            uint32_t ah[2][4], al[2][4], bh[8][2], bl[8][2];
            #pragma unroll
            for (int mt = 0; mt < 2; ++mt) {
                const int r0 = (mbase + mt * 16 + g) * LP + kb + tc;
                ah[mt][0] = *(const uint32_t*)&sAhi[r0];
                ah[mt][1] = *(const uint32_t*)&sAhi[r0 + 8 * LP];
                ah[mt][2] = *(const uint32_t*)&sAhi[r0 + 8];
                ah[mt][3] = *(const uint32_t*)&sAhi[r0 + 8 * LP + 8];
                al[mt][0] = *(const uint32_t*)&sAlo[r0];
                al[mt][1] = *(const uint32_t*)&sAlo[r0 + 8 * LP];
                al[mt][2] = *(const uint32_t*)&sAlo[r0 + 8];
                al[mt][3] = *(const uint32_t*)&sAlo[r0 + 8 * LP + 8];
            }
            #pragma unroll
            for (int nt = 0; nt < 8; ++nt) {
                const int rn = (nbase + nt * 8 + g) * LP + kb + tc;
                bh[nt][0] = *(const uint32_t*)&sBhi[rn];
                bh[nt][1] = *(const uint32_t*)&sBhi[rn + 8];
                bl[nt][0] = *(const uint32_t*)&sBlo[rn];
                bl[nt][1] = *(const uint32_t*)&sBlo[rn + 8];
            }
            #pragma unroll
            for (int mt = 0; mt < 2; ++mt)
                #pragma unroll
                for (int nt = 0; nt < 8; ++nt) {
                    mma16816(acc[mt][nt], ah[mt], bh[nt]);
                    mma16816(acc[mt][nt], ah[mt], bl[nt]);
                    mma16816(acc[mt][nt], al[mt], bh[nt]);
                }
        }
        __syncthreads();
    }

    // Epilogue: bias + store (float2 per 16x8 tile half)
    #pragma unroll
    for (int mt = 0; mt < 2; ++mt) {
        const int r0 = m0 + mbase + mt * 16 + g;
        #pragma unroll
        for (int nt = 0; nt < 8; ++nt) {
            const int cidx = n0 + nbase + nt * 8 + tc;
            const float2 bv = *(const float2*)&bias[cidx];
            float2 v0, v1;
            v0.x = acc[mt][nt][0] + bv.x;
            v0.y = acc[mt][nt][1] + bv.y;
            v1.x = acc[mt][nt][2] + bv.x;
            v1.y = acc[mt][nt][3] + bv.y;
            *(float2*)&C[(size_t)r0 * NC + cidx]       = v0;
            *(float2*)&C[(size_t)(r0 + 8) * NC + cidx] = v1;
        }
    }
}

// ---------------------------------------------------------------------------
// loc = ref + off/normalizer, and in-place softmax of attn logits.
// ---------------------------------------------------------------------------
__global__ __launch_bounds__(256) void loc_softmax_kernel(
    const float* __restrict__ refp, float* __restrict__ out)
{
    const int bq = blockIdx.x;
    const int t  = threadIdx.x;
    {
        const int xy = t & 1;
        const int l  = (t >> 3) & 3;
        const float offv = g_off[bq * 256 + t];
        const float ref  = refp[(bq * NL + l) * 2 + xy];
        const float norm = (float)c_HW[l];
        out[LOC_OFF + bq * 256 + t] = ref + offv / norm;
    }
    if (t < 128) {
        const int idx = ATTN_OFF + bq * 128 + t;
        float v = out[idx];
        float m = v;
        #pragma unroll
        for (int s = 8; s; s >>= 1)
            m = fmaxf(m, __shfl_xor_sync(0xffffffffu, m, s, 16));
        float e = __expf(v - m);
        float sum = e;
        #pragma unroll
        for (int s = 8; s; s >>= 1)
            sum += __shfl_xor_sync(0xffffffffu, sum, s, 16);
        out[idx] = e / sum;
    }
}

// ---------------------------------------------------------------------------
// Deformable bilinear sampling core.
// ---------------------------------------------------------------------------
__global__ __launch_bounds__(256) void deform_core_kernel(const float* __restrict__ out)
{
    const int bq   = blockIdx.x;
    const int b    = bq / NQ;
    const int h    = threadIdx.x >> 5;
    const int lane = threadIdx.x & 31;

    const float* loc  = out + LOC_OFF  + bq * 256 + h * 32;
    const float* attn = out + ATTN_OFF + bq * 128 + h * 16;

    float acc = 0.f;
    #pragma unroll
    for (int l = 0; l < NL; ++l) {
        const int W = c_HW[l];
        const int H = W;
        const int s0 = c_LSI[l];
        const int base = (b * NKTOT + s0) * DIM + h * 32 + lane;

        #pragma unroll
        for (int p = 0; p < NPNT; ++p) {
            const float lx = loc[(l * 4 + p) * 2 + 0];
            const float ly = loc[(l * 4 + p) * 2 + 1];
            const float a  = attn[l * 4 + p];

            const float x = lx * W - 0.5f;
            const float y = ly * H - 0.5f;
            const float x0f = floorf(x);
            const float y0f = floorf(y);
            const int x0 = (int)x0f;
            const int y0 = (int)y0f;
            const float fx = x - x0f;
            const float fy = y - y0f;

            const bool xv0 = (x0 >= 0)     && (x0 < W);
            const bool xv1 = (x0 + 1 >= 0) && (x0 + 1 < W);
            const bool yv0 = (y0 >= 0)     && (y0 < H);
            const bool yv1 = (y0 + 1 >= 0) && (y0 + 1 < H);

            float s = 0.f;
            if (yv0) {
                const int r = base + y0 * W * DIM;
                if (xv0) s += (1.f - fx) * (1.f - fy) * g_value[r + x0 * DIM];
                if (xv1) s += fx * (1.f - fy) * g_value[r + (x0 + 1) * DIM];
            }
            if (yv1) {
                const int r = base + (y0 + 1) * W * DIM;
                if (xv0) s += (1.f - fx) * fy * g_value[r + x0 * DIM];
                if (xv1) s += fx * fy * g_value[r + (x0 + 1) * DIM];
            }
            acc = fmaf(a, s, acc);
        }
    }
    g_core[bq * 256 + h * 32 + lane] = acc;
}

// ---------------------------------------------------------------------------
extern "C" void kernel_launch(void* const* d_in, const int* in_sizes, int n_in,
                              void* d_out, int out_size)
{
    const float* query = (const float*)d_in[0];
    const float* refp  = (const float*)d_in[1];
    const float* inpf  = (const float*)d_in[2];
    const float* Wv    = (const float*)d_in[5];
    const float* bv    = (const float*)d_in[6];
    const float* Woff  = (const float*)d_in[7];
    const float* boff  = (const float*)d_in[8];
    const float* Wattn = (const float*)d_in[9];
    const float* battn = (const float*)d_in[10];
    const float* Wout  = (const float*)d_in[11];
    const float* bout  = (const float*)d_in[12];
    float* out = (float*)d_out;

    float *valuep, *offp, *corep;
    __nv_bfloat16 *wthi, *wtlo;
    cudaGetSymbolAddress((void**)&valuep, g_value);
    cudaGetSymbolAddress((void**)&offp,   g_off);
    cudaGetSymbolAddress((void**)&corep,  g_core);
    cudaGetSymbolAddress((void**)&wthi,   g_wthi);
    cudaGetSymbolAddress((void**)&wtlo,   g_wtlo);

    // 0) transpose + bf16-split all weights
    prep_weights<<<dim3(256, 4), 256>>>(Wv, Woff, Wattn, Wout);

    const dim3 blk(256);
    const dim3 grid2(2, BQ / 128);   // N=256
    const dim3 grid1(1, BQ / 128);   // N=128

    // 1) value = input_flatten @ Wv + bv
    gemm_mma<256><<<grid2, blk>>>(inpf, wthi + 0 * 65536, wtlo + 0 * 65536, bv, valuep);
    // 2) off = query @ Woff + boff
    gemm_mma<256><<<grid2, blk>>>(query, wthi + 1 * 65536, wtlo + 1 * 65536, boff, offp);
    // 3) attn logits = query @ Wattn + battn
    gemm_mma<128><<<grid1, blk>>>(query, wthi + 2 * 65536, wtlo + 2 * 65536, battn, out + ATTN_OFF);
    // 4) loc + in-place softmax
    loc_softmax_kernel<<<BQ, blk>>>(refp, out);
    // 5) deformable bilinear core
    deform_core_kernel<<<BQ, blk>>>(out);
    // 6) output = core @ Wout + bout
    gemm_mma<256><<<grid2, blk>>>(corep, wthi + 3 * 65536, wtlo + 3 * 65536, bout, out + OUT_OFF);
}

// round 14
// speedup vs baseline: 1.0064x; 1.0064x over previous
#include <cuda_runtime.h>
#include <cuda_bf16.h>
#include <cstdint>

// Problem constants (fixed by the dataset)
#define BB    2
#define NQ    21760
#define NKTOT 21760
#define DIM   256
#define NH    8
#define NL    4
#define NPNT  4
#define BQ    (BB * NQ)            // 43520

// Hardcoded level geometry (SHAPES = [(128,128),(64,64),(32,32),(16,16)])
__device__ __constant__ int c_HW[NL]  = {128, 64, 32, 16};
__device__ __constant__ int c_LSI[NL] = {0, 16384, 20480, 21504};

// Output layout: [output | loc | attn]
#define OUT_OFF  0
#define LOC_OFF  (BQ * DIM)
#define ATTN_OFF (BQ * DIM * 2)

// Scratch (allocation-free: device globals)
__device__ float g_value[BQ * DIM];
__device__ float g_off[BQ * DIM];
__device__ float g_core[BQ * DIM];
// Pre-transposed, bf16-split weights: [w][N][K] with K=256, N<=256
__device__ __nv_bfloat16 g_wthi[4 * 256 * 256];
__device__ __nv_bfloat16 g_wtlo[4 * 256 * 256];

// fp32 -> (hi, lo) bf16 pair, packed 2-at-a-time
__device__ __forceinline__ void cvt2_split(float a, float b, uint32_t& hi, uint32_t& lo) {
    __nv_bfloat162 h = __floats2bfloat162_rn(a, b);
    float ra = a - __bfloat162float(h.x);
    float rb = b - __bfloat162float(h.y);
    __nv_bfloat162 l = __floats2bfloat162_rn(ra, rb);
    hi = *reinterpret_cast<uint32_t*>(&h);
    lo = *reinterpret_cast<uint32_t*>(&l);
}

// m16n8k16 bf16 MMA, fp32 accumulate (HMMA; valid on base sm_103 target)
__device__ __forceinline__ void mma16816(float* c, const uint32_t* a, const uint32_t* b) {
    asm volatile(
        "mma.sync.aligned.m16n8k16.row.col.f32.bf16.bf16.f32 "
        "{%0,%1,%2,%3}, {%4,%5,%6,%7}, {%8,%9}, {%0,%1,%2,%3};\n"
        : "+f"(c[0]), "+f"(c[1]), "+f"(c[2]), "+f"(c[3])
        : "r"(a[0]), "r"(a[1]), "r"(a[2]), "r"(a[3]), "r"(b[0]), "r"(b[1]));
}

// ---------------------------------------------------------------------------
// Weight prep: Wt[n][k] = split(W[k][n]) for the 4 weight matrices.
// ---------------------------------------------------------------------------
__global__ void prep_weights(const float* __restrict__ Wv, const float* __restrict__ Woff,
                             const float* __restrict__ Wattn, const float* __restrict__ Wout)
{
    const int w = blockIdx.y;
    const int n = blockIdx.x;
    const int Nw = (w == 2) ? 128 : 256;
    if (n >= Nw) return;
    const float* W = (w == 0) ? Wv : (w == 1) ? Woff : (w == 2) ? Wattn : Wout;
    const int k = threadIdx.x;
    const float v = W[k * Nw + n];
    const __nv_bfloat16 h = __float2bfloat16(v);
    g_wthi[w * 65536 + n * 256 + k] = h;
    g_wtlo[w * 65536 + n * 256 + k] = __float2bfloat16(v - __bfloat162float(h));
}

// ---------------------------------------------------------------------------
// bf16x3 HMMA GEMM: C[M, NC] = A[M, 256] @ Wt^T + bias  (Wt is [NC, 256] bf16)
// CTA: 256 thr = 8 warps (4 M x 2 N), tile 128x128, warp tile 32x64.
// K staged in 32-chunks; A split fp32->bf16 hi/lo during staging.
// Smem rows padded to 40 elems -> conflict-free m16n8k16 fragment loads.
// ---------------------------------------------------------------------------
template<int NC>
__global__ __launch_bounds__(256) void gemm_mma(
    const float* __restrict__ A,
    const __nv_bfloat16* __restrict__ Bhi_g, const __nv_bfloat16* __restrict__ Blo_g,
    const float* __restrict__ bias, float* __restrict__ C)
{
    constexpr int LP = 40;  // padded smem row stride (bf16 elements)
    __shared__ __align__(16) __nv_bfloat16 sAhi[128 * LP];
    __shared__ __align__(16) __nv_bfloat16 sAlo[128 * LP];
    __shared__ __align__(16) __nv_bfloat16 sBhi[128 * LP];
    __shared__ __align__(16) __nv_bfloat16 sBlo[128 * LP];

    const int t     = threadIdx.x;
    const int lane  = t & 31;
    const int warp  = t >> 5;
    const int warpM = warp & 3;          // 0..3
    const int warpN = warp >> 2;         // 0..1
    const int g     = lane >> 2;         // 0..7
    const int tc    = (lane & 3) << 1;   // 0,2,4,6
    const int m0    = blockIdx.y * 128;
    const int n0    = blockIdx.x * 128;
    const int mbase = warpM * 32;
    const int nbase = warpN * 64;

    float acc[2][8][4];
    #pragma unroll
    for (int i = 0; i < 2; ++i)
        #pragma unroll
        for (int j = 0; j < 8; ++j)
            #pragma unroll
            for (int k = 0; k < 4; ++k) acc[i][j][k] = 0.f;

    for (int kc = 0; kc < 256; kc += 32) {
        // Stage A: 128x32 fp32 -> hi/lo bf16 (4 float4 per thread)
        #pragma unroll
        for (int i = 0; i < 4; ++i) {
            const int idx = t + i * 256;
            const int row = idx >> 3;
            const int col = (idx & 7) << 2;
            const float4 f = *(const float4*)&A[(size_t)(m0 + row) * 256 + kc + col];
            uint32_t h0, l0, h1, l1;
            cvt2_split(f.x, f.y, h0, l0);
            cvt2_split(f.z, f.w, h1, l1);
            const int off = row * LP + col;
            *(uint32_t*)&sAhi[off]     = h0;
            *(uint32_t*)&sAhi[off + 2] = h1;
            *(uint32_t*)&sAlo[off]     = l0;
            *(uint32_t*)&sAlo[off + 2] = l1;
        }
        // Stage B: 128x32 bf16 hi/lo (2 uint4 per thread per tensor)
        #pragma unroll
        for (int i = 0; i < 2; ++i) {
            const int idx = t + i * 256;
            const int row = idx >> 2;
            const int col = (idx & 3) << 3;
            const uint4 h = *(const uint4*)&Bhi_g[(size_t)(n0 + row) * 256 + kc + col];
            const uint4 l = *(const uint4*)&Blo_g[(size_t)(n0 + row) * 256 + kc + col];
            const int off = row * LP + col;
            *(uint2*)&sBhi[off]     = make_uint2(h.x, h.y);
            *(uint2*)&sBhi[off + 4] = make_uint2(h.z, h.w);
            *(uint2*)&sBlo[off]     = make_uint2(l.x, l.y);
            *(uint2*)&sBlo[off + 4] = make_uint2(l.z, l.w);
        }
        __syncthreads();

        #pragma unroll
        for (int ks = 0; ks < 2; ++ks) {
            const int kb = ks * 16;
            uint32_t ah[2][4], al[2][4], bh[8][2], bl[8][2];
            #pragma unroll
            for (int mt = 0; mt < 2; ++mt) {
                const int r0 = (mbase + mt * 16 + g) * LP + kb + tc;
                ah[mt][0] = *(const uint32_t*)&sAhi[r0];
                ah[mt][1] = *(const uint32_t*)&sAhi[r0 + 8 * LP];
                ah[mt][2] = *(const uint32_t*)&sAhi[r0 + 8];
                ah[mt][3] = *(const uint32_t*)&sAhi[r0 + 8 * LP + 8];
                al[mt][0] = *(const uint32_t*)&sAlo[r0];
                al[mt][1] = *(const uint32_t*)&sAlo[r0 + 8 * LP];
                al[mt][2] = *(const uint32_t*)&sAlo[r0 + 8];
                al[mt][3] = *(const uint32_t*)&sAlo[r0 + 8 * LP + 8];
            }
            #pragma unroll
            for (int nt = 0; nt < 8; ++nt) {
                const int rn = (nbase + nt * 8 + g) * LP + kb + tc;
                bh[nt][0] = *(const uint32_t*)&sBhi[rn];
                bh[nt][1] = *(const uint32_t*)&sBhi[rn + 8];
                bl[nt][0] = *(const uint32_t*)&sBlo[rn];
                bl[nt][1] = *(const uint32_t*)&sBlo[rn + 8];
            }
            #pragma unroll
            for (int mt = 0; mt < 2; ++mt)
                #pragma unroll
                for (int nt = 0; nt < 8; ++nt) {
                    mma16816(acc[mt][nt], ah[mt], bh[nt]);
                    mma16816(acc[mt][nt], ah[mt], bl[nt]);
                    mma16816(acc[mt][nt], al[mt], bh[nt]);
                }
        }
        __syncthreads();
    }

    // Epilogue: bias + store (float2 per 16x8 tile half)
    #pragma unroll
    for (int mt = 0; mt < 2; ++mt) {
        const int r0 = m0 + mbase + mt * 16 + g;
        #pragma unroll
        for (int nt = 0; nt < 8; ++nt) {
            const int cidx = n0 + nbase + nt * 8 + tc;
            const float2 bv = *(const float2*)&bias[cidx];
            float2 v0, v1;
            v0.x = acc[mt][nt][0] + bv.x;
            v0.y = acc[mt][nt][1] + bv.y;
            v1.x = acc[mt][nt][2] + bv.x;
            v1.y = acc[mt][nt][3] + bv.y;
            *(float2*)&C[(size_t)r0 * NC + cidx]       = v0;
            *(float2*)&C[(size_t)(r0 + 8) * NC + cidx] = v1;
        }
    }
}

// ---------------------------------------------------------------------------
// loc = ref + off/normalizer, and in-place softmax of attn logits.
// ---------------------------------------------------------------------------
__global__ __launch_bounds__(256) void loc_softmax_kernel(
    const float* __restrict__ refp, float* __restrict__ out)
{
    const int bq = blockIdx.x;
    const int t  = threadIdx.x;
    {
        const int xy = t & 1;
        const int l  = (t >> 3) & 3;
        const float offv = g_off[bq * 256 + t];
        const float ref  = refp[(bq * NL + l) * 2 + xy];
        const float norm = (float)c_HW[l];
        out[LOC_OFF + bq * 256 + t] = ref + offv / norm;
    }
    if (t < 128) {
        const int idx = ATTN_OFF + bq * 128 + t;
        float v = out[idx];
        float m = v;
        #pragma unroll
        for (int s = 8; s; s >>= 1)
            m = fmaxf(m, __shfl_xor_sync(0xffffffffu, m, s, 16));
        float e = __expf(v - m);
        float sum = e;
        #pragma unroll
        for (int s = 8; s; s >>= 1)
            sum += __shfl_xor_sync(0xffffffffu, sum, s, 16);
        out[idx] = e / sum;
    }
}

// ---------------------------------------------------------------------------
// Deformable bilinear sampling core.
// ---------------------------------------------------------------------------
__global__ __launch_bounds__(256) void deform_core_kernel(const float* __restrict__ out)
{
    const int bq   = blockIdx.x;
    const int b    = bq / NQ;
    const int h    = threadIdx.x >> 5;
    const int lane = threadIdx.x & 31;

    const float* loc  = out + LOC_OFF  + bq * 256 + h * 32;
    const float* attn = out + ATTN_OFF + bq * 128 + h * 16;

    float acc = 0.f;
    #pragma unroll
    for (int l = 0; l < NL; ++l) {
        const int W = c_HW[l];
        const int H = W;
        const int s0 = c_LSI[l];
        const int base = (b * NKTOT + s0) * DIM + h * 32 + lane;

        #pragma unroll
        for (int p = 0; p < NPNT; ++p) {
            const float lx = loc[(l * 4 + p) * 2 + 0];
            const float ly = loc[(l * 4 + p) * 2 + 1];
            const float a  = attn[l * 4 + p];

            const float x = lx * W - 0.5f;
            const float y = ly * H - 0.5f;
            const float x0f = floorf(x);
            const float y0f = floorf(y);
            const int x0 = (int)x0f;
            const int y0 = (int)y0f;
            const float fx = x - x0f;
            const float fy = y - y0f;

            const bool xv0 = (x0 >= 0)     && (x0 < W);
            const bool xv1 = (x0 + 1 >= 0) && (x0 + 1 < W);
            const bool yv0 = (y0 >= 0)     && (y0 < H);
            const bool yv1 = (y0 + 1 >= 0) && (y0 + 1 < H);

            float s = 0.f;
            if (yv0) {
                const int r = base + y0 * W * DIM;
                if (xv0) s += (1.f - fx) * (1.f - fy) * g_value[r + x0 * DIM];
                if (xv1) s += fx * (1.f - fy) * g_value[r + (x0 + 1) * DIM];
            }
            if (yv1) {
                const int r = base + (y0 + 1) * W * DIM;
                if (xv0) s += (1.f - fx) * fy * g_value[r + x0 * DIM];
                if (xv1) s += fx * fy * g_value[r + (x0 + 1) * DIM];
            }
            acc = fmaf(a, s, acc);
        }
    }
    g_core[bq * 256 + h * 32 + lane] = acc;
}

// ---------------------------------------------------------------------------
extern "C" void kernel_launch(void* const* d_in, const int* in_sizes, int n_in,
                              void* d_out, int out_size)
{
    const float* query = (const float*)d_in[0];
    const float* refp  = (const float*)d_in[1];
    const float* inpf  = (const float*)d_in[2];
    const float* Wv    = (const float*)d_in[5];
    const float* bv    = (const float*)d_in[6];
    const float* Woff  = (const float*)d_in[7];
    const float* boff  = (const float*)d_in[8];
    const float* Wattn = (const float*)d_in[9];
    const float* battn = (const float*)d_in[10];
    const float* Wout  = (const float*)d_in[11];
    const float* bout  = (const float*)d_in[12];
    float* out = (float*)d_out;

    float *valuep, *offp, *corep;
    __nv_bfloat16 *wthi, *wtlo;
    cudaGetSymbolAddress((void**)&valuep, g_value);
    cudaGetSymbolAddress((void**)&offp,   g_off);
    cudaGetSymbolAddress((void**)&corep,  g_core);
    cudaGetSymbolAddress((void**)&wthi,   g_wthi);
    cudaGetSymbolAddress((void**)&wtlo,   g_wtlo);

    // 0) transpose + bf16-split all weights
    prep_weights<<<dim3(256, 4), 256>>>(Wv, Woff, Wattn, Wout);

    const dim3 blk(256);
    const dim3 grid2(2, BQ / 128);   // N=256
    const dim3 grid1(1, BQ / 128);   // N=128

    // 1) value = input_flatten @ Wv + bv
    gemm_mma<256><<<grid2, blk>>>(inpf, wthi + 0 * 65536, wtlo + 0 * 65536, bv, valuep);
    // 2) off = query @ Woff + boff
    gemm_mma<256><<<grid2, blk>>>(query, wthi + 1 * 65536, wtlo + 1 * 65536, boff, offp);
    // 3) attn logits = query @ Wattn + battn
    gemm_mma<128><<<grid1, blk>>>(query, wthi + 2 * 65536, wtlo + 2 * 65536, battn, out + ATTN_OFF);
    // 4) loc + in-place softmax
    loc_softmax_kernel<<<BQ, blk>>>(refp, out);
    // 5) deformable bilinear core
    deform_core_kernel<<<BQ, blk>>>(out);
    // 6) output = core @ Wout + bout
    gemm_mma<256><<<grid2, blk>>>(corep, wthi + 3 * 65536, wtlo + 3 * 65536, bout, out + OUT_OFF);
}

// round 15
// speedup vs baseline: 1.0081x; 1.0017x over previous
#include <cuda_runtime.h>
#include <cuda_bf16.h>
#include <cstdint>

// Problem constants (fixed by the dataset)
#define BB    2
#define NQ    21760
#define NKTOT 21760
#define DIM   256
#define NH    8
#define NL    4
#define NPNT  4
#define BQ    (BB * NQ)            // 43520

// Hardcoded level geometry (SHAPES = [(128,128),(64,64),(32,32),(16,16)])
__device__ __constant__ int c_HW[NL]  = {128, 64, 32, 16};
__device__ __constant__ int c_LSI[NL] = {0, 16384, 20480, 21504};

// Output layout: [output | loc | attn]
#define OUT_OFF  0
#define LOC_OFF  (BQ * DIM)
#define ATTN_OFF (BQ * DIM * 2)

// Scratch (allocation-free: device globals)
__device__ float g_value[BQ * DIM];
__device__ float g_off[BQ * DIM];
__device__ float g_core[BQ * DIM];
// Pre-transposed, bf16-split weights: [w][N][K] with K=256, N<=256
__device__ __nv_bfloat16 g_wthi[4 * 256 * 256];
__device__ __nv_bfloat16 g_wtlo[4 * 256 * 256];

// fp32 -> (hi, lo) bf16 pair, packed 2-at-a-time
__device__ __forceinline__ void cvt2_split(float a, float b, uint32_t& hi, uint32_t& lo) {
    __nv_bfloat162 h = __floats2bfloat162_rn(a, b);
    float ra = a - __bfloat162float(h.x);
    float rb = b - __bfloat162float(h.y);
    __nv_bfloat162 l = __floats2bfloat162_rn(ra, rb);
    hi = *reinterpret_cast<uint32_t*>(&h);
    lo = *reinterpret_cast<uint32_t*>(&l);
}

// m16n8k16 bf16 MMA, fp32 accumulate (HMMA; valid on base sm_103 target)
__device__ __forceinline__ void mma16816(float* c, const uint32_t* a, const uint32_t* b) {
    asm volatile(
        "mma.sync.aligned.m16n8k16.row.col.f32.bf16.bf16.f32 "
        "{%0,%1,%2,%3}, {%4,%5,%6,%7}, {%8,%9}, {%0,%1,%2,%3};\n"
        : "+f"(c[0]), "+f"(c[1]), "+f"(c[2]), "+f"(c[3])
        : "r"(a[0]), "r"(a[1]), "r"(a[2]), "r"(a[3]), "r"(b[0]), "r"(b[1]));
}

// ---------------------------------------------------------------------------
// Weight prep: Wt[n][k] = split(W[k][n]) for the 4 weight matrices.
// ---------------------------------------------------------------------------
__global__ void prep_weights(const float* __restrict__ Wv, const float* __restrict__ Woff,
                             const float* __restrict__ Wattn, const float* __restrict__ Wout)
{
    const int w = blockIdx.y;
    const int n = blockIdx.x;
    const int Nw = (w == 2) ? 128 : 256;
    if (n >= Nw) return;
    const float* W = (w == 0) ? Wv : (w == 1) ? Woff : (w == 2) ? Wattn : Wout;
    const int k = threadIdx.x;
    const float v = W[k * Nw + n];
    const __nv_bfloat16 h = __float2bfloat16(v);
    g_wthi[w * 65536 + n * 256 + k] = h;
    g_wtlo[w * 65536 + n * 256 + k] = __float2bfloat16(v - __bfloat162float(h));
}

// ---------------------------------------------------------------------------
// bf16x3 HMMA GEMM: C[M, NC] = A[M, 256] @ Wt^T + bias  (Wt is [NC, 256] bf16)
// CTA: 256 thr = 8 warps (4 M x 2 N), tile 128x128, warp tile 32x64.
// K staged in 32-chunks; A split fp32->bf16 hi/lo during staging.
// Smem rows padded to 40 elems -> conflict-free m16n8k16 fragment loads.
// ---------------------------------------------------------------------------
template<int NC>
__global__ __launch_bounds__(256) void gemm_mma(
    const float* __restrict__ A,
    const __nv_bfloat16* __restrict__ Bhi_g, const __nv_bfloat16* __restrict__ Blo_g,
    const float* __restrict__ bias, float* __restrict__ C)
{
    constexpr int LP = 40;  // padded smem row stride (bf16 elements)
    __shared__ __align__(16) __nv_bfloat16 sAhi[128 * LP];
    __shared__ __align__(16) __nv_bfloat16 sAlo[128 * LP];
    __shared__ __align__(16) __nv_bfloat16 sBhi[128 * LP];
    __shared__ __align__(16) __nv_bfloat16 sBlo[128 * LP];

    const int t     = threadIdx.x;
    const int lane  = t & 31;
    const int warp  = t >> 5;
    const int warpM = warp & 3;          // 0..3
    const int warpN = warp >> 2;         // 0..1
    const int g     = lane >> 2;         // 0..7
    const int tc    = (lane & 3) << 1;   // 0,2,4,6
    const int m0    = blockIdx.y * 128;
    const int n0    = blockIdx.x * 128;
    const int mbase = warpM * 32;
    const int nbase = warpN * 64;

    float acc[2][8][4];
    #pragma unroll
    for (int i = 0; i < 2; ++i)
        #pragma unroll
        for (int j = 0; j < 8; ++j)
            #pragma unroll
            for (int k = 0; k < 4; ++k) acc[i][j][k] = 0.f;

    for (int kc = 0; kc < 256; kc += 32) {
        // Stage A: 128x32 fp32 -> hi/lo bf16 (4 float4 per thread)
        #pragma unroll
        for (int i = 0; i < 4; ++i) {
            const int idx = t + i * 256;
            const int row = idx >> 3;
            const int col = (idx & 7) << 2;
            const float4 f = *(const float4*)&A[(size_t)(m0 + row) * 256 + kc + col];
            uint32_t h0, l0, h1, l1;
            cvt2_split(f.x, f.y, h0, l0);
            cvt2_split(f.z, f.w, h1, l1);
            const int off = row * LP + col;
            *(uint32_t*)&sAhi[off]     = h0;
            *(uint32_t*)&sAhi[off + 2] = h1;
            *(uint32_t*)&sAlo[off]     = l0;
            *(uint32_t*)&sAlo[off + 2] = l1;
        }
        // Stage B: 128x32 bf16 hi/lo (2 uint4 per thread per tensor)
        #pragma unroll
        for (int i = 0; i < 2; ++i) {
            const int idx = t + i * 256;
            const int row = idx >> 2;
            const int col = (idx & 3) << 3;
            const uint4 h = *(const uint4*)&Bhi_g[(size_t)(n0 + row) * 256 + kc + col];
            const uint4 l = *(const uint4*)&Blo_g[(size_t)(n0 + row) * 256 + kc + col];
            const int off = row * LP + col;
            *(uint2*)&sBhi[off]     = make_uint2(h.x, h.y);
            *(uint2*)&sBhi[off + 4] = make_uint2(h.z, h.w);
            *(uint2*)&sBlo[off]     = make_uint2(l.x, l.y);
            *(uint2*)&sBlo[off + 4] = make_uint2(l.z, l.w);
        }
        __syncthreads();

        #pragma unroll
        for (int ks = 0; ks < 2; ++ks) {
            const int kb = ks * 16;
            uint32_t ah[2][4], al[2][4], bh[8][2], bl[8][2];
            #pragma unroll
            for (int mt = 0; mt < 2; ++mt) {
                const int r0 = (mbase + mt * 16 + g) * LP + kb + tc;
                ah[mt][0] = *(const uint32_t*)&sAhi[r0];
                ah[mt][1] = *(const uint32_t*)&sAhi[r0 + 8 * LP];
                ah[mt][2] = *(const uint32_t*)&sAhi[r0 + 8];
                ah[mt][3] = *(const uint32_t*)&sAhi[r0 + 8 * LP + 8];
                al[mt][0] = *(const uint32_t*)&sAlo[r0];
                al[mt][1] = *(const uint32_t*)&sAlo[r0 + 8 * LP];
                al[mt][2] = *(const uint32_t*)&sAlo[r0 + 8];
                al[mt][3] = *(const uint32_t*)&sAlo[r0 + 8 * LP + 8];
            }
            #pragma unroll
            for (int nt = 0; nt < 8; ++nt) {
                const int rn = (nbase + nt * 8 + g) * LP + kb + tc;
                bh[nt][0] = *(const uint32_t*)&sBhi[rn];
                bh[nt][1] = *(const uint32_t*)&sBhi[rn + 8];
                bl[nt][0] = *(const uint32_t*)&sBlo[rn];
                bl[nt][1] = *(const uint32_t*)&sBlo[rn + 8];
            }
            #pragma unroll
            for (int mt = 0; mt < 2; ++mt)
                #pragma unroll
                for (int nt = 0; nt < 8; ++nt) {
                    mma16816(acc[mt][nt], ah[mt], bh[nt]);
                    mma16816(acc[mt][nt], ah[mt], bl[nt]);
                    mma16816(acc[mt][nt], al[mt], bh[nt]);
                }
        }
        __syncthreads();
    }

    // Epilogue: bias + store (float2 per 16x8 tile half)
    #pragma unroll
    for (int mt = 0; mt < 2; ++mt) {
        const int r0 = m0 + mbase + mt * 16 + g;
        #pragma unroll
        for (int nt = 0; nt < 8; ++nt) {
            const int cidx = n0 + nbase + nt * 8 + tc;
            const float2 bv = *(const float2*)&bias[cidx];
            float2 v0, v1;
            v0.x = acc[mt][nt][0] + bv.x;
            v0.y = acc[mt][nt][1] + bv.y;
            v1.x = acc[mt][nt][2] + bv.x;
            v1.y = acc[mt][nt][3] + bv.y;
            *(float2*)&C[(size_t)r0 * NC + cidx]       = v0;
            *(float2*)&C[(size_t)(r0 + 8) * NC + cidx] = v1;
        }
    }
}

// ---------------------------------------------------------------------------
// loc = ref + off/normalizer, and in-place softmax of attn logits.
// ---------------------------------------------------------------------------
__global__ __launch_bounds__(256) void loc_softmax_kernel(
    const float* __restrict__ refp, float* __restrict__ out)
{
    const int bq = blockIdx.x;
    const int t  = threadIdx.x;
    {
        const int xy = t & 1;
        const int l  = (t >> 3) & 3;
        const float offv = g_off[bq * 256 + t];
        const float ref  = refp[(bq * NL + l) * 2 + xy];
        const float norm = (float)c_HW[l];
        out[LOC_OFF + bq * 256 + t] = ref + offv / norm;
    }
    if (t < 128) {
        const int idx = ATTN_OFF + bq * 128 + t;
        float v = out[idx];
        float m = v;
        #pragma unroll
        for (int s = 8; s; s >>= 1)
            m = fmaxf(m, __shfl_xor_sync(0xffffffffu, m, s, 16));
        float e = __expf(v - m);
        float sum = e;
        #pragma unroll
        for (int s = 8; s; s >>= 1)
            sum += __shfl_xor_sync(0xffffffffu, sum, s, 16);
        out[idx] = e / sum;
    }
}

// ---------------------------------------------------------------------------
// Deformable bilinear sampling core.
// ---------------------------------------------------------------------------
__global__ __launch_bounds__(256) void deform_core_kernel(const float* __restrict__ out)
{
    const int bq   = blockIdx.x;
    const int b    = bq / NQ;
    const int h    = threadIdx.x >> 5;
    const int lane = threadIdx.x & 31;

    const float* loc  = out + LOC_OFF  + bq * 256 + h * 32;
    const float* attn = out + ATTN_OFF + bq * 128 + h * 16;

    float acc = 0.f;
    #pragma unroll
    for (int l = 0; l < NL; ++l) {
        const int W = c_HW[l];
        const int H = W;
        const int s0 = c_LSI[l];
        const int base = (b * NKTOT + s0) * DIM + h * 32 + lane;

        #pragma unroll
        for (int p = 0; p < NPNT; ++p) {
            const float lx = loc[(l * 4 + p) * 2 + 0];
            const float ly = loc[(l * 4 + p) * 2 + 1];
            const float a  = attn[l * 4 + p];

            const float x = lx * W - 0.5f;
            const float y = ly * H - 0.5f;
            const float x0f = floorf(x);
            const float y0f = floorf(y);
            const int x0 = (int)x0f;
            const int y0 = (int)y0f;
            const float fx = x - x0f;
            const float fy = y - y0f;

            const bool xv0 = (x0 >= 0)     && (x0 < W);
            const bool xv1 = (x0 + 1 >= 0) && (x0 + 1 < W);
            const bool yv0 = (y0 >= 0)     && (y0 < H);
            const bool yv1 = (y0 + 1 >= 0) && (y0 + 1 < H);

            float s = 0.f;
            if (yv0) {
                const int r = base + y0 * W * DIM;
                if (xv0) s += (1.f - fx) * (1.f - fy) * g_value[r + x0 * DIM];
                if (xv1) s += fx * (1.f - fy) * g_value[r + (x0 + 1) * DIM];
            }
            if (yv1) {
                const int r = base + (y0 + 1) * W * DIM;
                if (xv0) s += (1.f - fx) * fy * g_value[r + x0 * DIM];
                if (xv1) s += fx * fy * g_value[r + (x0 + 1) * DIM];
            }
            acc = fmaf(a, s, acc);
        }
    }
    g_core[bq * 256 + h * 32 + lane] = acc;
}

// ---------------------------------------------------------------------------
extern "C" void kernel_launch(void* const* d_in, const int* in_sizes, int n_in,
                              void* d_out, int out_size)
{
    const float* query = (const float*)d_in[0];
    const float* refp  = (const float*)d_in[1];
    const float* inpf  = (const float*)d_in[2];
    const float* Wv    = (const float*)d_in[5];
    const float* bv    = (const float*)d_in[6];
    const float* Woff  = (const float*)d_in[7];
    const float* boff  = (const float*)d_in[8];
    const float* Wattn = (const float*)d_in[9];
    const float* battn = (const float*)d_in[10];
    const float* Wout  = (const float*)d_in[11];
    const float* bout  = (const float*)d_in[12];
    float* out = (float*)d_out;

    float *valuep, *offp, *corep;
    __nv_bfloat16 *wthi, *wtlo;
    cudaGetSymbolAddress((void**)&valuep, g_value);
    cudaGetSymbolAddress((void**)&offp,   g_off);
    cudaGetSymbolAddress((void**)&corep,  g_core);
    cudaGetSymbolAddress((void**)&wthi,   g_wthi);
    cudaGetSymbolAddress((void**)&wtlo,   g_wtlo);

    // 0) transpose + bf16-split all weights
    prep_weights<<<dim3(256, 4), 256>>>(Wv, Woff, Wattn, Wout);

    const dim3 blk(256);
    const dim3 grid2(2, BQ / 128);   // N=256
    const dim3 grid1(1, BQ / 128);   // N=128

    // 1) value = input_flatten @ Wv + bv
    gemm_mma<256><<<grid2, blk>>>(inpf, wthi + 0 * 65536, wtlo + 0 * 65536, bv, valuep);
    // 2) off = query @ Woff + boff
    gemm_mma<256><<<grid2, blk>>>(query, wthi + 1 * 65536, wtlo + 1 * 65536, boff, offp);
    // 3) attn logits = query @ Wattn + battn
    gemm_mma<128><<<grid1, blk>>>(query, wthi + 2 * 65536, wtlo + 2 * 65536, battn, out + ATTN_OFF);
    // 4) loc + in-place softmax
    loc_softmax_kernel<<<BQ, blk>>>(refp, out);
    // 5) deformable bilinear core
    deform_core_kernel<<<BQ, blk>>>(out);
    // 6) output = core @ Wout + bout
    gemm_mma<256><<<grid2, blk>>>(corep, wthi + 3 * 65536, wtlo + 3 * 65536, bout, out + OUT_OFF);
}